// round 10
// baseline (speedup 1.0000x reference)
#include <cuda_runtime.h>
#include <cuda_bf16.h>

#define N_SYSTEMS 16
#define D 64
#define NWARPS 8           // warps per block
#define NBLOCKS 888        // 148 SMs * 6 blocks (32.5 KB smem each)

// Global scratch. Zero-initialized at module load; the last block re-zeroes
// after consuming it, so the "zero at entry" invariant holds across graph
// replays without a dedicated zeroing launch.
__device__ float g_sums[N_SYSTEMS * D];
__device__ float g_counts[N_SYSTEMS];
__device__ unsigned int g_ticket;   // zero-init; reset by last block

// Warp processes a PAIR of rows per iteration:
//   lanes 0-15  -> row 2p   (float4 chunk lane)
//   lanes 16-31 -> row 2p+1 (float4 chunk lane-16)
// One LDG.128 warp-instruction = 512B = both rows, fully coalesced.
// Both system codes come from one broadcast int2 load (no cross-half SHFL).
// Accumulation into per-warp private shared buffers (no atomics).
// The LAST block to finish also computes the 16x16 distance epilogue
// (rides the grid tail instead of costing a separate launch).
__global__ void __launch_bounds__(256, 6) accumulate_kernel(
    const float* __restrict__ out, const int* __restrict__ system,
    float* __restrict__ dist, int n_rows)
{
    __shared__ float4 ssum4[NWARPS][N_SYSTEMS][16];  // 32 KB
    __shared__ float  scount[NWARPS][N_SYSTEMS];     // 512 B
    __shared__ int    s_last;

    const int tid  = threadIdx.x;
    const int lane = tid & 31;
    const int warp = tid >> 5;
    const int half = lane >> 4;      // 0 = row 2p, 1 = row 2p+1
    const int q    = lane & 15;      // float4 index within row

    // Zero private accumulators.
    {
        float4* z = &ssum4[0][0][0];
        for (int i = tid; i < NWARPS * N_SYSTEMS * 16; i += 256)
            z[i] = make_float4(0.f, 0.f, 0.f, 0.f);
        if (tid < NWARPS * N_SYSTEMS) (&scount[0][0])[tid] = 0.0f;
    }
    __syncthreads();

    const float4* __restrict__ out4 = (const float4*)out;
    const long long npairs = (long long)(n_rows + 1) >> 1;
    const long long total_warps = (long long)gridDim.x * NWARPS;
    long long p = (long long)blockIdx.x * NWARPS + warp;

    // Prefetch first pair.
    float4 v = make_float4(0.f, 0.f, 0.f, 0.f);
    int cA = -1, cB = -1;
    if (p < npairs) {
        v = __ldcs(&out4[p * 32 + lane]);
        int2 c = __ldg((const int2*)system + p);   // broadcast: both codes
        cA = c.x;
        cB = (2 * p + 1 < (long long)n_rows) ? c.y : -1;
    }

    while (p < npairs) {
        // Prefetch next pair.
        long long pn = p + total_warps;
        float4 vn = make_float4(0.f, 0.f, 0.f, 0.f);
        int cAn = -1, cBn = -1;
        if (pn < npairs) {
            vn = __ldcs(&out4[pn * 32 + lane]);
            int2 c = __ldg((const int2*)system + pn);
            cAn = c.x;
            cBn = (2 * pn + 1 < (long long)n_rows) ? c.y : -1;
        }

        // ---- process current pair ----
        const int code = half ? cB : cA;

        // Sum of squares per row: width-16 butterfly (covers both rows).
        float ss = v.x * v.x + v.y * v.y + v.z * v.z + v.w * v.w;
        ss += __shfl_xor_sync(0xFFFFFFFFu, ss, 8);
        ss += __shfl_xor_sync(0xFFFFFFFFu, ss, 4);
        ss += __shfl_xor_sync(0xFFFFFFFFu, ss, 2);
        ss += __shfl_xor_sync(0xFFFFFFFFu, ss, 1);
        const float inv = rsqrtf(fmaxf(ss, 1e-24f)); // == 1/max(||x||,1e-12)

        if (!(cA == cB && cA >= 0)) {
            // Common path: halves hit distinct systems (or one invalid).
            if (code >= 0) {
                float4 a = ssum4[warp][code][q];
                a.x = fmaf(v.x, inv, a.x);
                a.y = fmaf(v.y, inv, a.y);
                a.z = fmaf(v.z, inv, a.z);
                a.w = fmaf(v.w, inv, a.w);
                ssum4[warp][code][q] = a;
                if (q == 0) scount[warp][code] += 1.0f;  // lanes 0,16 differ
            }
        } else {
            // Rare path (~1/16): both halves same system; combine to lower.
            float4 s;
            s.x = v.x * inv; s.y = v.y * inv; s.z = v.z * inv; s.w = v.w * inv;
            s.x += __shfl_xor_sync(0xFFFFFFFFu, s.x, 16);
            s.y += __shfl_xor_sync(0xFFFFFFFFu, s.y, 16);
            s.z += __shfl_xor_sync(0xFFFFFFFFu, s.z, 16);
            s.w += __shfl_xor_sync(0xFFFFFFFFu, s.w, 16);
            if (half == 0) {
                float4 a = ssum4[warp][code][q];
                a.x += s.x; a.y += s.y; a.z += s.z; a.w += s.w;
                ssum4[warp][code][q] = a;
                if (q == 0) scount[warp][code] += 2.0f;
            }
        }

        v = vn; cA = cAn; cB = cBn; p = pn;
    }

    __syncthreads();

    // Block flush: reduce the NWARPS private copies, one global atomic each.
    const float* sf = (const float*)&ssum4[0][0][0];   // [NWARPS][1024]
    for (int i = tid; i < N_SYSTEMS * D; i += 256) {
        float acc = 0.0f;
        #pragma unroll
        for (int w = 0; w < NWARPS; w++) acc += sf[w * (N_SYSTEMS * D) + i];
        if (acc != 0.0f) atomicAdd(&g_sums[i], acc);
    }
    if (tid < N_SYSTEMS) {
        float c = 0.0f;
        #pragma unroll
        for (int w = 0; w < NWARPS; w++) c += scount[w][tid];
        if (c != 0.0f) atomicAdd(&g_counts[tid], c);
    }

    // ---- last-block epilogue ----
    __threadfence();
    if (tid == 0) {
        unsigned int t = atomicAdd(&g_ticket, 1u);
        s_last = (t == (unsigned)gridDim.x - 1u) ? 1 : 0;
    }
    __syncthreads();
    if (!s_last) return;

    // Reuse ssum4's first 1 KB region as 'means'.
    float* means = (float*)&ssum4[0][0][0];
    for (int i = tid; i < N_SYSTEMS * D; i += 256) {
        int s = i >> 6;              // i / D
        means[i] = g_sums[i] / g_counts[s];
    }
    __syncthreads();

    // Re-zero scratch for the next call/replay (all reads of g_* done).
    for (int i = tid; i < N_SYSTEMS * D; i += 256) g_sums[i] = 0.0f;
    if (tid < N_SYSTEMS) g_counts[tid] = 0.0f;
    if (tid == 0) g_ticket = 0u;

    int i = tid >> 4;
    int j = tid & 15;
    float dot = 0.0f;
    #pragma unroll
    for (int d = 0; d < D; d++)
        dot += means[i * D + d] * means[j * D + d];

    float val = 0.5f - 0.5f * dot;
    if (i == j) val = 0.0f;
    dist[i * N_SYSTEMS + j] = val;
}

extern "C" void kernel_launch(void* const* d_in, const int* in_sizes, int n_in,
                              void* d_out, int out_size) {
    const float* out_mat = (const float*)d_in[0];
    const int* system = (const int*)d_in[1];
    float* dist = (float*)d_out;
    int n_rows = in_sizes[1];  // system has one entry per row

    accumulate_kernel<<<NBLOCKS, 256>>>(out_mat, system, dist, n_rows);
}

// round 11
// speedup vs baseline: 1.0702x; 1.0702x over previous
#include <cuda_runtime.h>
#include <cuda_bf16.h>

#define N_SYSTEMS 16
#define D 64
#define NWARPS 8           // warps per block
#define NBLOCKS 888        // 148 SMs * 6 blocks (32.5 KB smem each)

// Global scratch. Zero-initialized at module load; finalize_kernel re-zeroes
// after each use, so the "zero at accumulate-entry" invariant holds across
// graph replays without a dedicated zeroing launch.
__device__ float g_sums[N_SYSTEMS * D];
__device__ float g_counts[N_SYSTEMS];

// Warp processes a PAIR of rows per iteration:
//   lanes 0-15  -> row 2p   (float4 chunk lane)
//   lanes 16-31 -> row 2p+1 (float4 chunk lane-16)
// One LDG.128 warp-instruction = 512B = both rows, fully coalesced.
// Both system codes come from one broadcast int2 load (no cross-half SHFL).
// Vector sums accumulate in per-warp private shared buffers (no atomics);
// COUNTS accumulate in pure registers (lane l counts system l), removing
// all count-related smem traffic from the hot loop.
__global__ void __launch_bounds__(256) accumulate_kernel(
    const float* __restrict__ out, const int* __restrict__ system, int n_rows)
{
    __shared__ float4 ssum4[NWARPS][N_SYSTEMS][16];  // 32 KB
    __shared__ float  scount[NWARPS][N_SYSTEMS];     // 512 B

    const int tid  = threadIdx.x;
    const int lane = tid & 31;
    const int warp = tid >> 5;
    const int half = lane >> 4;      // 0 = row 2p, 1 = row 2p+1
    const int q    = lane & 15;      // float4 index within row

    // Zero private accumulators.
    {
        float4* z = &ssum4[0][0][0];
        for (int i = tid; i < NWARPS * N_SYSTEMS * 16; i += 256)
            z[i] = make_float4(0.f, 0.f, 0.f, 0.f);
    }
    __syncthreads();

    const float4* __restrict__ out4 = (const float4*)out;
    const int npairs = (n_rows + 1) >> 1;            // fits int32
    const int total_warps = (int)gridDim.x * NWARPS;
    int p = (int)blockIdx.x * NWARPS + warp;

    int cnt = 0;   // lane l (l<16) counts rows of system l seen by this thread's warp

    // Prefetch first pair.
    float4 v = make_float4(0.f, 0.f, 0.f, 0.f);
    int cA = -1, cB = -1;
    if (p < npairs) {
        v = __ldcs(&out4[(size_t)p * 32 + lane]);
        int2 c = __ldg((const int2*)system + p);     // broadcast: both codes
        cA = c.x;
        cB = (2 * p + 1 < n_rows) ? c.y : -1;
    }

    while (p < npairs) {
        // Prefetch next pair.
        int pn = p + total_warps;
        float4 vn = make_float4(0.f, 0.f, 0.f, 0.f);
        int cAn = -1, cBn = -1;
        if (pn < npairs) {
            vn = __ldcs(&out4[(size_t)pn * 32 + lane]);
            int2 c = __ldg((const int2*)system + pn);
            cAn = c.x;
            cBn = (2 * pn + 1 < n_rows) ? c.y : -1;
        }

        // ---- process current pair ----
        const int code = half ? cB : cA;

        // Register count: each pair contributes +1 to cA and +1 to cB.
        cnt += (cA == lane) ? 1 : 0;
        cnt += (cB == lane) ? 1 : 0;

        // Sum of squares per row: width-16 butterfly (covers both rows).
        float ss = v.x * v.x + v.y * v.y + v.z * v.z + v.w * v.w;
        ss += __shfl_xor_sync(0xFFFFFFFFu, ss, 8);
        ss += __shfl_xor_sync(0xFFFFFFFFu, ss, 4);
        ss += __shfl_xor_sync(0xFFFFFFFFu, ss, 2);
        ss += __shfl_xor_sync(0xFFFFFFFFu, ss, 1);
        const float inv = rsqrtf(fmaxf(ss, 1e-24f)); // == 1/max(||x||,1e-12)

        if (!(cA == cB && cA >= 0)) {
            // Common path: halves hit distinct systems (or one invalid).
            if (code >= 0) {
                float4 a = ssum4[warp][code][q];
                a.x = fmaf(v.x, inv, a.x);
                a.y = fmaf(v.y, inv, a.y);
                a.z = fmaf(v.z, inv, a.z);
                a.w = fmaf(v.w, inv, a.w);
                ssum4[warp][code][q] = a;
            }
        } else {
            // Rare path (~1/16): both halves same system; combine to lower.
            float4 s;
            s.x = v.x * inv; s.y = v.y * inv; s.z = v.z * inv; s.w = v.w * inv;
            s.x += __shfl_xor_sync(0xFFFFFFFFu, s.x, 16);
            s.y += __shfl_xor_sync(0xFFFFFFFFu, s.y, 16);
            s.z += __shfl_xor_sync(0xFFFFFFFFu, s.z, 16);
            s.w += __shfl_xor_sync(0xFFFFFFFFu, s.w, 16);
            if (half == 0) {
                float4 a = ssum4[warp][code][q];
                a.x += s.x; a.y += s.y; a.z += s.z; a.w += s.w;
                ssum4[warp][code][q] = a;
            }
        }

        v = vn; cA = cAn; cB = cBn; p = pn;
    }

    // Park per-warp counts in smem for the block reduce.
    if (lane < N_SYSTEMS) scount[warp][lane] = (float)cnt;
    __syncthreads();

    // Block flush: reduce the NWARPS private copies, one global atomic each.
    const float* sf = (const float*)&ssum4[0][0][0];   // [NWARPS][1024]
    for (int i = tid; i < N_SYSTEMS * D; i += 256) {
        float acc = 0.0f;
        #pragma unroll
        for (int w = 0; w < NWARPS; w++) acc += sf[w * (N_SYSTEMS * D) + i];
        if (acc != 0.0f) atomicAdd(&g_sums[i], acc);
    }
    if (tid < N_SYSTEMS) {
        float c = 0.0f;
        #pragma unroll
        for (int w = 0; w < NWARPS; w++) c += scount[w][tid];
        if (c != 0.0f) atomicAdd(&g_counts[tid], c);
    }
}

// Single-block epilogue (1024 threads): means -> Gram -> distance matrix,
// then re-zero the global scratch for the next call/replay.
// 4 threads per (i,j) output pair: 16-dim partial dots + 2 shfl reduces.
__global__ void __launch_bounds__(1024) finalize_kernel(float* __restrict__ dist)
{
    __shared__ float means[N_SYSTEMS * D];
    const int t = threadIdx.x;

    // Load sums, divide by counts (1 element per thread).
    {
        int s = t >> 6;                 // t / D
        means[t] = g_sums[t] / g_counts[s];
    }
    __syncthreads();

    // Re-zero scratch (all reads of g_* are done).
    g_sums[t] = 0.0f;
    if (t < N_SYSTEMS) g_counts[t] = 0.0f;

    const int pair = t >> 2;            // 256 pairs
    const int sub  = t & 3;             // 16-dim slice
    const int i = pair >> 4;
    const int j = pair & 15;

    float dot = 0.0f;
    const float* mi = &means[i * D + sub * 16];
    const float* mj = &means[j * D + sub * 16];
    #pragma unroll
    for (int d = 0; d < 16; d++)
        dot = fmaf(mi[d], mj[d], dot);

    // Reduce the 4 sub-partials (threads t, t^1, t^2 are in the same warp).
    dot += __shfl_xor_sync(0xFFFFFFFFu, dot, 1);
    dot += __shfl_xor_sync(0xFFFFFFFFu, dot, 2);

    if (sub == 0) {
        float v = 0.5f - 0.5f * dot;
        if (i == j) v = 0.0f;
        dist[pair] = v;
    }
}

extern "C" void kernel_launch(void* const* d_in, const int* in_sizes, int n_in,
                              void* d_out, int out_size) {
    const float* out_mat = (const float*)d_in[0];
    const int* system = (const int*)d_in[1];
    float* dist = (float*)d_out;
    int n_rows = in_sizes[1];  // system has one entry per row

    accumulate_kernel<<<NBLOCKS, 256>>>(out_mat, system, n_rows);
    finalize_kernel<<<1, 1024>>>(dist);
}

// round 12
// speedup vs baseline: 1.0793x; 1.0085x over previous
#include <cuda_runtime.h>
#include <cuda_bf16.h>

#define N_SYSTEMS 16
#define D 64
#define NWARPS 8           // warps per block
#define NBLOCKS 888        // 148 SMs * 6 blocks (32.5 KB smem each)

// Global scratch. Zero-initialized at module load; finalize_kernel re-zeroes
// after each use, so the "zero at accumulate-entry" invariant holds across
// graph replays without a dedicated zeroing launch.
__device__ float g_sums[N_SYSTEMS * D];
__device__ float g_counts[N_SYSTEMS];

// Warp processes a PAIR of rows per iteration:
//   lanes 0-15  -> row 2p   (float4 chunk lane)
//   lanes 16-31 -> row 2p+1 (float4 chunk lane-16)
// One LDG.128 warp-instruction = 512B = both rows, fully coalesced.
// Both system codes come from one broadcast int2 load (no cross-half SHFL).
// Vector sums accumulate in per-warp private shared buffers (no atomics);
// counts accumulate in pure registers (lane l counts system l).
__global__ void __launch_bounds__(256) accumulate_kernel(
    const float* __restrict__ out, const int* __restrict__ system, int n_rows)
{
    __shared__ float4 ssum4[NWARPS][N_SYSTEMS][16];  // 32 KB
    __shared__ float  scount[NWARPS][N_SYSTEMS];     // 512 B

    const int tid  = threadIdx.x;
    const int lane = tid & 31;
    const int warp = tid >> 5;
    const int half = lane >> 4;      // 0 = row 2p, 1 = row 2p+1
    const int q    = lane & 15;      // float4 index within row

    // Zero private accumulators.
    {
        float4* z = &ssum4[0][0][0];
        for (int i = tid; i < NWARPS * N_SYSTEMS * 16; i += 256)
            z[i] = make_float4(0.f, 0.f, 0.f, 0.f);
    }
    __syncthreads();

    const float4* __restrict__ out4 = (const float4*)out;
    const int npairs = (n_rows + 1) >> 1;            // fits int32
    const int total_warps = (int)gridDim.x * NWARPS;
    int p = (int)blockIdx.x * NWARPS + warp;

    int cnt = 0;   // lane l (l<16) counts rows of system l seen by this warp

    // Prefetch first pair.
    float4 v = make_float4(0.f, 0.f, 0.f, 0.f);
    int cA = -1, cB = -1;
    if (p < npairs) {
        v = __ldcs(&out4[(size_t)p * 32 + lane]);
        int2 c = __ldg((const int2*)system + p);     // broadcast: both codes
        cA = c.x;
        cB = (2 * p + 1 < n_rows) ? c.y : -1;
    }

    while (p < npairs) {
        // Prefetch next pair.
        int pn = p + total_warps;
        float4 vn = make_float4(0.f, 0.f, 0.f, 0.f);
        int cAn = -1, cBn = -1;
        if (pn < npairs) {
            vn = __ldcs(&out4[(size_t)pn * 32 + lane]);
            int2 c = __ldg((const int2*)system + pn);
            cAn = c.x;
            cBn = (2 * pn + 1 < n_rows) ? c.y : -1;
        }

        // ---- process current pair ----
        const int code = half ? cB : cA;

        // Register count: each pair contributes +1 to cA and +1 to cB.
        cnt += (cA == lane) ? 1 : 0;
        cnt += (cB == lane) ? 1 : 0;

        // Sum of squares per row: width-16 butterfly (covers both rows).
        float ss = v.x * v.x + v.y * v.y + v.z * v.z + v.w * v.w;
        ss += __shfl_xor_sync(0xFFFFFFFFu, ss, 8);
        ss += __shfl_xor_sync(0xFFFFFFFFu, ss, 4);
        ss += __shfl_xor_sync(0xFFFFFFFFu, ss, 2);
        ss += __shfl_xor_sync(0xFFFFFFFFu, ss, 1);
        const float inv = rsqrtf(fmaxf(ss, 1e-24f)); // == 1/max(||x||,1e-12)

        if (!(cA == cB && cA >= 0)) {
            // Common path: halves hit distinct systems (or one invalid).
            if (code >= 0) {
                float4 a = ssum4[warp][code][q];
                a.x = fmaf(v.x, inv, a.x);
                a.y = fmaf(v.y, inv, a.y);
                a.z = fmaf(v.z, inv, a.z);
                a.w = fmaf(v.w, inv, a.w);
                ssum4[warp][code][q] = a;
            }
        } else {
            // Rare path (~1/16): both halves same system; combine to lower.
            float4 s;
            s.x = v.x * inv; s.y = v.y * inv; s.z = v.z * inv; s.w = v.w * inv;
            s.x += __shfl_xor_sync(0xFFFFFFFFu, s.x, 16);
            s.y += __shfl_xor_sync(0xFFFFFFFFu, s.y, 16);
            s.z += __shfl_xor_sync(0xFFFFFFFFu, s.z, 16);
            s.w += __shfl_xor_sync(0xFFFFFFFFu, s.w, 16);
            if (half == 0) {
                float4 a = ssum4[warp][code][q];
                a.x += s.x; a.y += s.y; a.z += s.z; a.w += s.w;
                ssum4[warp][code][q] = a;
            }
        }

        v = vn; cA = cAn; cB = cBn; p = pn;
    }

    // Park per-warp counts in smem for the block reduce.
    if (lane < N_SYSTEMS) scount[warp][lane] = (float)cnt;
    __syncthreads();

    // Block flush: reduce the NWARPS private copies, one global atomic each.
    const float* sf = (const float*)&ssum4[0][0][0];   // [NWARPS][1024]
    for (int i = tid; i < N_SYSTEMS * D; i += 256) {
        float acc = 0.0f;
        #pragma unroll
        for (int w = 0; w < NWARPS; w++) acc += sf[w * (N_SYSTEMS * D) + i];
        if (acc != 0.0f) atomicAdd(&g_sums[i], acc);
    }
    if (tid < N_SYSTEMS) {
        float c = 0.0f;
        #pragma unroll
        for (int w = 0; w < NWARPS; w++) c += scount[w][tid];
        if (c != 0.0f) atomicAdd(&g_counts[tid], c);
    }

    // Let the PDL-dependent finalize kernel's blocks launch now; its
    // cudaGridDependencySynchronize still waits for this grid's completion.
    cudaTriggerProgrammaticLaunchCompletion();
}

// Single-block epilogue (1024 threads): means -> Gram -> distance matrix,
// then re-zero the global scratch for the next call/replay.
// Launched with programmatic stream serialization: its block is resident
// before accumulate finishes; the grid-dependency sync makes all of
// accumulate's atomics visible before g_sums is read.
__global__ void __launch_bounds__(1024) finalize_kernel(float* __restrict__ dist)
{
    cudaGridDependencySynchronize();

    __shared__ float means[N_SYSTEMS * D];
    const int t = threadIdx.x;

    // Load sums, divide by counts (1 element per thread).
    {
        int s = t >> 6;                 // t / D
        means[t] = g_sums[t] / g_counts[s];
    }
    __syncthreads();

    // Re-zero scratch (all reads of g_* are done).
    g_sums[t] = 0.0f;
    if (t < N_SYSTEMS) g_counts[t] = 0.0f;

    const int pair = t >> 2;            // 256 pairs
    const int sub  = t & 3;             // 16-dim slice
    const int i = pair >> 4;
    const int j = pair & 15;

    float dot = 0.0f;
    const float* mi = &means[i * D + sub * 16];
    const float* mj = &means[j * D + sub * 16];
    #pragma unroll
    for (int d = 0; d < 16; d++)
        dot = fmaf(mi[d], mj[d], dot);

    // Reduce the 4 sub-partials (threads t, t^1, t^2 are in the same warp).
    dot += __shfl_xor_sync(0xFFFFFFFFu, dot, 1);
    dot += __shfl_xor_sync(0xFFFFFFFFu, dot, 2);

    if (sub == 0) {
        float v = 0.5f - 0.5f * dot;
        if (i == j) v = 0.0f;
        dist[pair] = v;
    }
}

extern "C" void kernel_launch(void* const* d_in, const int* in_sizes, int n_in,
                              void* d_out, int out_size) {
    const float* out_mat = (const float*)d_in[0];
    const int* system = (const int*)d_in[1];
    float* dist = (float*)d_out;
    int n_rows = in_sizes[1];  // system has one entry per row

    accumulate_kernel<<<NBLOCKS, 256>>>(out_mat, system, n_rows);

    // PDL launch of the epilogue: overlap its launch/scheduling with the
    // accumulate grid's tail.
    cudaLaunchConfig_t cfg = {};
    cfg.gridDim = dim3(1, 1, 1);
    cfg.blockDim = dim3(1024, 1, 1);
    cfg.dynamicSmemBytes = 0;
    cudaLaunchAttribute attr[1];
    attr[0].id = cudaLaunchAttributeProgrammaticStreamSerialization;
    attr[0].val.programmaticStreamSerializationAllowed = 1;
    cfg.attrs = attr;
    cfg.numAttrs = 1;
    cudaLaunchKernelEx(&cfg, finalize_kernel, dist);
}